// round 3
// baseline (speedup 1.0000x reference)
#include <cuda_runtime.h>
#include <cstdint>

#define DD 64
#define LL 128
#define KROWS 8192
#define RPB 64
#define NBLK (KROWS/RPB)
#define HSTR 68
#define NTHR 512

typedef unsigned long long u64;

__device__ float g_a[256];
__device__ float g_cb[256];
__device__ float g_Wt[64*256];
__device__ float g_acc[128];

__device__ __forceinline__ float fexp(float x){
    x = fmaxf(fminf(x, 30.f), -30.f);
    return __expf(x);
}
__device__ __forceinline__ float sigf(float x){
    return __fdividef(1.0f, 1.0f + fexp(-x));
}
__device__ __forceinline__ float tanhp(float x){
    return 2.0f * __fdividef(1.0f, 1.0f + fexp(-2.0f*x)) - 1.0f;
}

__device__ __forceinline__ u64 pack2(float lo, float hi){
    u64 r; asm("mov.b64 %0, {%1, %2};" : "=l"(r) : "f"(lo), "f"(hi)); return r;
}
__device__ __forceinline__ float2 unpack2(u64 v){
    float2 r; asm("mov.b64 {%0, %1}, %2;" : "=f"(r.x), "=f"(r.y) : "l"(v)); return r;
}
__device__ __forceinline__ void ffma2(u64 &d, u64 a, u64 b){
    asm("fma.rn.f32x2 %0, %1, %2, %0;" : "+l"(d) : "l"(a), "l"(b));
}

__global__ void prep_kernel(const float* __restrict__ W_ih, const float* __restrict__ W_num,
                            const float* __restrict__ b_num, const float* __restrict__ b_ih,
                            const float* __restrict__ b_hh, const float* __restrict__ W_hh){
    int g = threadIdx.x;   // 0..255
    float sa = 0.f, sc = 0.f;
    #pragma unroll 8
    for (int d = 0; d < DD; d++){
        float w = W_ih[g*(2*DD)+d];
        sa += w * W_num[d];
        sc += w * b_num[d];
    }
    g_a[g]  = sa;
    g_cb[g] = sc + b_ih[g] + b_hh[g];
    #pragma unroll 8
    for (int k = 0; k < DD; k++) g_Wt[k*256+g] = W_hh[g*DD+k];
    if (g < 128) g_acc[g] = 0.f;
}

__global__ void __launch_bounds__(NTHR,1)
lstm_kernel(const float* __restrict__ x,
            const float* __restrict__ W_aout, const float* __restrict__ b_aout,
            const float* __restrict__ W_fh,  const float* __restrict__ b_fh){
    extern __shared__ float sm[];
    float* sWt  = sm;                   // 16384: Wt[k][g]
    float* sH0  = sm + 16384;           // 64*HSTR: h[d][r]
    float* sH1  = sH0 + 64*HSTR;        // 64*HSTR (double buffer)
    float* sA   = sH1 + 64*HSTR;        // 256
    float* sC   = sA + 256;             // 256
    float* sRed = sC + 256;             // 128
    float* sX   = sRed + 128;           // 8192: x[r][t]

    int tid = threadIdx.x;
    const int r0 = blockIdx.x * RPB;
    for (int i = tid; i < 16384;     i += NTHR) sWt[i] = g_Wt[i];
    for (int i = tid; i < 2*64*HSTR; i += NTHR) sH0[i] = 0.f;
    for (int i = tid; i < RPB*LL;    i += NTHR) sX[i]  = x[(size_t)r0*LL + i];
    if (tid < 256){ sA[tid] = g_a[tid]; sC[tid] = g_cb[tid]; }
    if (tid < 128) sRed[tid] = 0.f;
    __syncthreads();

    const int tx = tid & 15;       // d-tile: d = tx*4 + j
    const int ty = tid >> 4;       // r-tile: r = ty*2 + i  (ty 0..31)

    float cst[2][4];
    #pragma unroll
    for (int i = 0; i < 2; i++)
        #pragma unroll
        for (int j = 0; j < 4; j++) cst[i][j] = 0.f;

    float* bufs[2] = {sH0, sH1};

    for (int t = 0; t < LL; t++){
        float* sHr = bufs[t & 1];
        float* sHw = bufs[(t + 1) & 1];

        u64 ai[2][2], af[2][2], ag[2][2], ao[2][2];
        #pragma unroll
        for (int i = 0; i < 2; i++)
            #pragma unroll
            for (int jp = 0; jp < 2; jp++){ ai[i][jp]=0ull; af[i][jp]=0ull; ag[i][jp]=0ull; ao[i][jp]=0ull; }

        #pragma unroll 2
        for (int k = 0; k < DD; k++){
            float2 hv = *(const float2*)(sHr + k*HSTR + (ty<<1));
            const u64* wr2 = (const u64*)(sWt + (k<<8));
            ulonglong2 wi = *(const ulonglong2*)(wr2 +      (tx<<1));
            ulonglong2 wf = *(const ulonglong2*)(wr2 + 32 + (tx<<1));
            ulonglong2 wg = *(const ulonglong2*)(wr2 + 64 + (tx<<1));
            ulonglong2 wo = *(const ulonglong2*)(wr2 + 96 + (tx<<1));
            u64 h0 = pack2(hv.x, hv.x);
            u64 h1 = pack2(hv.y, hv.y);
            ffma2(ai[0][0], h0, wi.x);  ffma2(ai[0][1], h0, wi.y);
            ffma2(af[0][0], h0, wf.x);  ffma2(af[0][1], h0, wf.y);
            ffma2(ag[0][0], h0, wg.x);  ffma2(ag[0][1], h0, wg.y);
            ffma2(ao[0][0], h0, wo.x);  ffma2(ao[0][1], h0, wo.y);
            ffma2(ai[1][0], h1, wi.x);  ffma2(ai[1][1], h1, wi.y);
            ffma2(af[1][0], h1, wf.x);  ffma2(af[1][1], h1, wf.y);
            ffma2(ag[1][0], h1, wg.x);  ffma2(ag[1][1], h1, wg.y);
            ffma2(ao[1][0], h1, wo.x);  ffma2(ao[1][1], h1, wo.y);
        }

        float hn[2][4];
        #pragma unroll
        for (int i = 0; i < 2; i++){
            float xv = sX[(((ty<<1)+i)<<7) + t];
            float aif[4], aff[4], agf[4], aof[4];
            { float2 p0 = unpack2(ai[i][0]), p1 = unpack2(ai[i][1]);
              aif[0]=p0.x; aif[1]=p0.y; aif[2]=p1.x; aif[3]=p1.y; }
            { float2 p0 = unpack2(af[i][0]), p1 = unpack2(af[i][1]);
              aff[0]=p0.x; aff[1]=p0.y; aff[2]=p1.x; aff[3]=p1.y; }
            { float2 p0 = unpack2(ag[i][0]), p1 = unpack2(ag[i][1]);
              agf[0]=p0.x; agf[1]=p0.y; agf[2]=p1.x; agf[3]=p1.y; }
            { float2 p0 = unpack2(ao[i][0]), p1 = unpack2(ao[i][1]);
              aof[0]=p0.x; aof[1]=p0.y; aof[2]=p1.x; aof[3]=p1.y; }
            #pragma unroll
            for (int j = 0; j < 4; j++){
                int d = (tx<<2) + j;
                float gi = aif[j] + sA[d      ]*xv + sC[d      ];
                float gf = aff[j] + sA[ 64 + d]*xv + sC[ 64 + d];
                float gg = agf[j] + sA[128 + d]*xv + sC[128 + d];
                float go = aof[j] + sA[192 + d]*xv + sC[192 + d];
                float c2 = sigf(gf)*cst[i][j] + sigf(gi)*tanhp(gg);
                cst[i][j] = c2;
                hn[i][j] = sigf(go)*tanhp(c2);
            }
        }
        #pragma unroll
        for (int j = 0; j < 4; j++){
            *(float2*)(sHw + ((tx<<2)+j)*HSTR + (ty<<1)) =
                make_float2(hn[0][j], hn[1][j]);
        }
        __syncthreads();
    }

    float* sH = bufs[0];   // after 128 steps, final h is in buffer 0

    // ----- final per-CTA stage -----
    float* sHhat = sWt;            // [e][r] stride HSTR
    float* sWa   = sWt + 8192;     // W_aout transposed: [e][d]
    float* sWf   = sWt + 12288;    // W_fh  transposed: [e][d]
    for (int i = tid; i < 4096; i += NTHR){
        int dd = i & 63;
        int ee = i >> 6;
        sWa[i] = W_aout[dd*64 + ee];
        sWf[i] = W_fh  [dd*64 + ee];
    }
    __syncthreads();

    // h_hat[r][d] = sum_e h[r][e] * W_aout[d][e] + b_aout[d]
    float hh[2][4];
    #pragma unroll
    for (int j = 0; j < 4; j++){
        float b = __ldg(b_aout + (tx<<2) + j);
        hh[0][j] = b; hh[1][j] = b;
    }
    #pragma unroll 4
    for (int e = 0; e < DD; e++){
        float2 hv = *(const float2*)(sH + e*HSTR + (ty<<1));
        float4 wv = *(const float4*)(sWa + e*64 + (tx<<2));
        float w[4] = {wv.x, wv.y, wv.z, wv.w};
        #pragma unroll
        for (int j = 0; j < 4; j++){
            hh[0][j] += hv.x*w[j];
            hh[1][j] += hv.y*w[j];
        }
    }
    float hsb[4];
    #pragma unroll
    for (int j = 0; j < 4; j++){
        hsb[j] = hh[0][j] + hh[1][j];
        *(float2*)(sHhat + ((tx<<2)+j)*HSTR + (ty<<1)) =
            make_float2(hh[0][j], hh[1][j]);
    }
    __syncthreads();

    // f[r][d] = sum_e h_hat[r][e] * W_fh[d][e] + b_fh[d]
    float ff[2][4];
    #pragma unroll
    for (int j = 0; j < 4; j++){
        float b = __ldg(b_fh + (tx<<2) + j);
        ff[0][j] = b; ff[1][j] = b;
    }
    #pragma unroll 4
    for (int e = 0; e < DD; e++){
        float2 hv = *(const float2*)(sHhat + e*HSTR + (ty<<1));
        float4 wv = *(const float4*)(sWf + e*64 + (tx<<2));
        float w[4] = {wv.x, wv.y, wv.z, wv.w};
        #pragma unroll
        for (int j = 0; j < 4; j++){
            ff[0][j] += hv.x*w[j];
            ff[1][j] += hv.y*w[j];
        }
    }
    #pragma unroll
    for (int j = 0; j < 4; j++){
        float fcp = sigf(ff[0][j])*cst[0][j] + sigf(ff[1][j])*cst[1][j];
        atomicAdd(&sRed[     (tx<<2)+j], fcp);
        atomicAdd(&sRed[64 + (tx<<2)+j], hsb[j]);
    }
    __syncthreads();
    if (tid < 128) atomicAdd(&g_acc[tid], sRed[tid]);
}

__global__ void fin_kernel(const float* __restrict__ W_iouh, const float* __restrict__ b_iouh,
                           const float* __restrict__ W_oout, const float* __restrict__ b_oout,
                           float* __restrict__ out){
    __shared__ float sfc[64], shs[64], sho[64];
    int d = threadIdx.x;   // 0..63
    sfc[d] = g_acc[d];
    shs[d] = g_acc[64 + d];
    __syncthreads();
    float vi = b_iouh[d], vo = b_iouh[64 + d], vu = b_iouh[128 + d];
    #pragma unroll 8
    for (int e = 0; e < DD; e++){
        float h = shs[e];
        vi += h * W_iouh[(      d)*64 + e];
        vo += h * W_iouh[( 64 + d)*64 + e];
        vu += h * W_iouh[(128 + d)*64 + e];
    }
    float cobj = sigf(vi)*tanhp(vu) + sfc[d];
    sho[d] = sigf(vo)*tanhp(cobj);
    __syncthreads();
    float acc = b_oout[d];
    #pragma unroll 8
    for (int e = 0; e < DD; e++) acc += sho[e] * W_oout[d*64 + e];
    out[d]      = acc;
    out[64 + d] = cobj;
}

extern "C" void kernel_launch(void* const* d_in, const int* in_sizes, int n_in,
                              void* d_out, int out_size){
    const float* x      = (const float*)d_in[0];
    const float* W_num  = (const float*)d_in[1];
    const float* b_num  = (const float*)d_in[2];
    const float* W_ih   = (const float*)d_in[3];
    const float* W_hh   = (const float*)d_in[4];
    const float* b_ih   = (const float*)d_in[5];
    const float* b_hh   = (const float*)d_in[6];
    const float* W_aout = (const float*)d_in[7];
    const float* b_aout = (const float*)d_in[8];
    const float* W_fh   = (const float*)d_in[9];
    const float* b_fh   = (const float*)d_in[10];
    const float* W_iouh = (const float*)d_in[11];
    const float* b_iouh = (const float*)d_in[12];
    const float* W_oout = (const float*)d_in[13];
    const float* b_oout = (const float*)d_in[14];
    float* out = (float*)d_out;

    size_t smem = (16384 + 2*64*HSTR + 256 + 256 + 128 + 8192) * sizeof(float);
    cudaFuncSetAttribute(lstm_kernel, cudaFuncAttributeMaxDynamicSharedMemorySize, (int)smem);

    prep_kernel<<<1, 256>>>(W_ih, W_num, b_num, b_ih, b_hh, W_hh);
    lstm_kernel<<<NBLK, NTHR, smem>>>(x, W_aout, b_aout, W_fh, b_fh);
    fin_kernel<<<1, 64>>>(W_iouh, b_iouh, W_oout, b_oout, out);
}

// round 6
// speedup vs baseline: 4.3136x; 4.3136x over previous
#include <cuda_runtime.h>
#include <cuda_bf16.h>
#include <cstdint>

#define DD 64
#define LL 128
#define KROWS 8192
#define MROWS 64
#define NBLK (KROWS/MROWS)   // 128 CTAs
#define NTHR 256

typedef unsigned int u32;

// smem byte offsets
#define SM_A0H 0          // h buf0 hi: 64 rows x 128B
#define SM_A0L 8192
#define SM_A1H 16384
#define SM_A1L 24576
#define SM_BH  32768      // B hi: 256 n-rows x 128B
#define SM_BL  65536
#define SM_X   98304      // x: 64 x 129 floats = 33024B
#define SM_CA  131328     // a consts, 256 floats
#define SM_CB  132352     // cb consts, 256 floats
#define SM_RED 133376     // 128 floats
#define SM_TOT 133952

__device__ float g_a[256];
__device__ float g_cb[256];
__device__ __nv_bfloat16 g_Bhi[256*64];
__device__ __nv_bfloat16 g_Blo[256*64];
__device__ float g_acc[128];

__device__ __forceinline__ float fexp(float x){
    x = fmaxf(fminf(x, 30.f), -30.f);
    return __expf(x);
}
__device__ __forceinline__ float sigf(float x){
    return __fdividef(1.0f, 1.0f + fexp(-x));
}
__device__ __forceinline__ float tanhp(float x){
    return 2.0f * __fdividef(1.0f, 1.0f + fexp(-2.0f*x)) - 1.0f;
}

__device__ __forceinline__ void mma_bf16(float* c, const u32* a, const u32* b){
    asm volatile("mma.sync.aligned.m16n8k16.row.col.f32.bf16.bf16.f32 "
        "{%0,%1,%2,%3}, {%4,%5,%6,%7}, {%8,%9}, {%0,%1,%2,%3};\n"
        : "+f"(c[0]),"+f"(c[1]),"+f"(c[2]),"+f"(c[3])
        : "r"(a[0]),"r"(a[1]),"r"(a[2]),"r"(a[3]), "r"(b[0]),"r"(b[1]));
}

// ---------- prep: collapsed input proj + reordered, pre-swizzled split-bf16 W_hh^T ----------
// Column order: n = wn*128 + j*8 + c, j in 0..15; gate G = j>>2; dl = (j&3)*8+c; d = wn*32+dl.
__global__ void prep_kernel(const float* __restrict__ W_ih, const float* __restrict__ W_num,
                            const float* __restrict__ b_num, const float* __restrict__ b_ih,
                            const float* __restrict__ b_hh, const float* __restrict__ W_hh){
    int n = threadIdx.x;            // 0..255
    int wn = n >> 7;
    int rem = n & 127;
    int j = rem >> 3;
    int c = rem & 7;
    int G = j >> 2;
    int dl = (j & 3)*8 + c;
    int d  = wn*32 + dl;
    int wr = G*64 + d;
    float sa = 0.f, sc = 0.f;
    #pragma unroll 8
    for (int k = 0; k < DD; k++){
        float w = W_ih[wr*(2*DD) + k];
        sa += w * W_num[k];
        sc += w * b_num[k];
    }
    g_a[n]  = sa;
    g_cb[n] = sc + b_ih[wr] + b_hh[wr];
    #pragma unroll 8
    for (int k = 0; k < DD; k++){
        float w = W_hh[wr*DD + k];
        __nv_bfloat16 hi = __float2bfloat16(w);
        __nv_bfloat16 lo = __float2bfloat16(w - __bfloat162float(hi));
        u32 off = (u32)n*128 + (u32)k*2;
        u32 sw  = off ^ (((u32)n & 7u) << 4);
        g_Bhi[sw >> 1] = hi;
        g_Blo[sw >> 1] = lo;
    }
    if (n < 128) g_acc[n] = 0.f;
}

// ---------- main LSTM: warp-level HMMA ----------
__global__ void __launch_bounds__(NTHR,1)
lstm_kernel(const float* __restrict__ x,
            const float* __restrict__ W_aout, const float* __restrict__ b_aout,
            const float* __restrict__ W_fh,  const float* __restrict__ b_fh){
    extern __shared__ char sm[];
    const int tid  = threadIdx.x;
    const int wid  = tid >> 5;
    const int lane = tid & 31;
    const int g    = lane >> 2;      // group 0..7
    const int tq   = lane & 3;       // quad  0..3
    const int mt   = wid & 3;        // m-tile 0..3 (rows mt*16..)
    const int wn   = wid >> 2;       // n-half 0/1
    const u32 xorv = (u32)g << 4;
    const int r0   = blockIdx.x * MROWS;

    float* sXf = (float*)(sm + SM_X);
    float* sCa = (float*)(sm + SM_CA);
    float* sCb = (float*)(sm + SM_CB);
    float* sRd = (float*)(sm + SM_RED);

    // ---- init ----
    {
        uint4* db = (uint4*)(sm + SM_BH);
        const uint4* sb = (const uint4*)g_Bhi;
        for (int i = tid; i < 2048; i += NTHR) db[i] = sb[i];
        uint4* dl2 = (uint4*)(sm + SM_BL);
        const uint4* sl = (const uint4*)g_Blo;
        for (int i = tid; i < 2048; i += NTHR) dl2[i] = sl[i];
        uint4 z = make_uint4(0,0,0,0);
        uint4* da = (uint4*)(sm + SM_A0H);
        for (int i = tid; i < 2048; i += NTHR) da[i] = z;       // all 4 A buffers (32KB)
        for (int idx = tid; idx < MROWS*LL; idx += NTHR){
            int rr = idx >> 7, tt = idx & 127;
            sXf[rr*129 + tt] = x[(size_t)(r0 + rr)*LL + tt];
        }
        if (tid < 256){ sCa[tid] = g_a[tid]; sCb[tid] = g_cb[tid]; }
        if (tid < 128) sRd[tid] = 0.f;
    }
    __syncthreads();

    float creg[16];
    #pragma unroll
    for (int i = 0; i < 16; i++) creg[i] = 0.f;

    const char* Bh0 = sm + SM_BH + (size_t)((wn*128 + g) * 128);
    const char* Bl0 = sm + SM_BL + (size_t)((wn*128 + g) * 128);

    for (int t = 0; t < LL; t++){
        const char* Ah = sm + ((t & 1) ? SM_A1H : SM_A0H);
        const char* Al = Ah + 8192;
        char* AwH = sm + ((t & 1) ? SM_A0H : SM_A1H);
        char* AwL = AwH + 8192;
        // this warp's A base: rows mt*16 + (g / g+8)
        const char* ArH = Ah + mt*2048 + g*128;
        const char* ArL = Al + mt*2048 + g*128;

        float acc[64];
        #pragma unroll
        for (int i = 0; i < 64; i++) acc[i] = 0.f;

        #pragma unroll
        for (int K0 = 0; K0 < 64; K0 += 16){
            u32 o0 = ((u32)(2*K0 + 4*tq)) ^ xorv;
            u32 o8 = o0 ^ 16u;
            u32 ah[4], al[4];
            ah[0] = *(const u32*)(ArH +        o0);
            ah[1] = *(const u32*)(ArH + 1024 + o0);
            ah[2] = *(const u32*)(ArH +        o8);
            ah[3] = *(const u32*)(ArH + 1024 + o8);
            al[0] = *(const u32*)(ArL +        o0);
            al[1] = *(const u32*)(ArL + 1024 + o0);
            al[2] = *(const u32*)(ArL +        o8);
            al[3] = *(const u32*)(ArL + 1024 + o8);
            #pragma unroll
            for (int j = 0; j < 16; j++){
                u32 bh[2], bl[2];
                bh[0] = *(const u32*)(Bh0 + j*1024 + o0);
                bh[1] = *(const u32*)(Bh0 + j*1024 + o8);
                bl[0] = *(const u32*)(Bl0 + j*1024 + o0);
                bl[1] = *(const u32*)(Bl0 + j*1024 + o8);
                mma_bf16(acc + j*4, ah, bh);
                mma_bf16(acc + j*4, ah, bl);
                mma_bf16(acc + j*4, al, bh);
            }
        }

        // ---- epilogue: gates -> (c,h), write h bf16 hi/lo ----
        float xv0 = sXf[(mt*16 + g    )*129 + t];
        float xv1 = sXf[(mt*16 + g + 8)*129 + t];
        #pragma unroll
        for (int q = 0; q < 4; q++){
            int nI = wn*128 + q*8 + 2*tq;
            float2 aI = *(const float2*)(sCa + nI     );
            float2 aF = *(const float2*)(sCa + nI + 32);
            float2 aG = *(const float2*)(sCa + nI + 64);
            float2 aO = *(const float2*)(sCa + nI + 96);
            float2 cI = *(const float2*)(sCb + nI     );
            float2 cF = *(const float2*)(sCb + nI + 32);
            float2 cG = *(const float2*)(sCb + nI + 64);
            float2 cO = *(const float2*)(sCb + nI + 96);
            #pragma unroll
            for (int s = 0; s < 2; s++){
                float xv = s ? xv1 : xv0;
                float h2[2];
                #pragma unroll
                for (int u = 0; u < 2; u++){
                    int fi = s*2 + u;
                    float gi = acc[( q    )*4 + fi] + (u?aI.y:aI.x)*xv + (u?cI.y:cI.x);
                    float gf = acc[( 4+q  )*4 + fi] + (u?aF.y:aF.x)*xv + (u?cF.y:cF.x);
                    float gg = acc[( 8+q  )*4 + fi] + (u?aG.y:aG.x)*xv + (u?cG.y:cG.x);
                    float go = acc[(12+q  )*4 + fi] + (u?aO.y:aO.x)*xv + (u?cO.y:cO.x);
                    int ci = q*4 + fi;
                    float c2 = sigf(gf)*creg[ci] + sigf(gi)*tanhp(gg);
                    creg[ci] = c2;
                    h2[u] = sigf(go)*tanhp(c2);
                }
                __nv_bfloat16 b0 = __float2bfloat16(h2[0]);
                __nv_bfloat16 b1 = __float2bfloat16(h2[1]);
                u32 hp = (u32)__bfloat16_as_ushort(b0) | ((u32)__bfloat16_as_ushort(b1) << 16);
                __nv_bfloat16 l0 = __float2bfloat16(h2[0] - __bfloat162float(b0));
                __nv_bfloat16 l1 = __float2bfloat16(h2[1] - __bfloat162float(b1));
                u32 lp = (u32)__bfloat16_as_ushort(l0) | ((u32)__bfloat16_as_ushort(l1) << 16);
                int r = mt*16 + g + s*8;
                u32 cbS = ((u32)(wn*64 + q*16 + 4*tq)) ^ xorv;
                *(u32*)(AwH + r*128 + cbS) = hp;
                *(u32*)(AwL + r*128 + cbS) = lp;
            }
        }
        __syncthreads();
    }

    // ---- final per-CTA stage ----
    // reconstruct fp32 h (from buf0 hi/lo) and dump c-state
    float* sHfin = (float*)(sm + SM_X);            // [row][d] stride 64
    float* sCst  = (float*)(sm + SM_X + 16384);
    #pragma unroll
    for (int q = 0; q < 4; q++){
        #pragma unroll
        for (int s = 0; s < 2; s++){
            #pragma unroll
            for (int u = 0; u < 2; u++){
                int r  = mt*16 + g + s*8;
                int dl = q*8 + 2*tq + u;
                int d  = wn*32 + dl;
                u32 sw = ((u32)(2*d)) ^ xorv;
                float h = __bfloat162float(*(const __nv_bfloat16*)(sm + SM_A0H + r*128 + sw))
                        + __bfloat162float(*(const __nv_bfloat16*)(sm + SM_A0L + r*128 + sw));
                sHfin[r*64 + d] = h;
                sCst [r*64 + d] = creg[q*4 + s*2 + u];
            }
        }
    }
    // stage W_aout / W_fh over the B region
    float* sWa = (float*)(sm + SM_BH);
    float* sWf = sWa + 4096;
    for (int i = tid; i < 4096; i += NTHR){ sWa[i] = W_aout[i]; sWf[i] = W_fh[i]; }
    __syncthreads();

    float* sHhat = (float*)(sm + SM_A0H);          // [row][d] stride 64 (16KB)
    const int row = tid >> 2;
    const int d0  = (tid & 3) << 4;
    #pragma unroll 2
    for (int jj = 0; jj < 16; jj++){
        int d = d0 + jj;
        float acc2 = __ldg(b_aout + d);
        #pragma unroll 8
        for (int e = 0; e < DD; e++) acc2 += sHfin[row*64 + e] * sWa[d*64 + e];
        sHhat[row*64 + d] = acc2;
        atomicAdd(&sRd[64 + d], acc2);
    }
    __syncthreads();
    #pragma unroll 2
    for (int jj = 0; jj < 16; jj++){
        int d = d0 + jj;
        float f = __ldg(b_fh + d);
        #pragma unroll 8
        for (int e = 0; e < DD; e++) f += sHhat[row*64 + e] * sWf[d*64 + e];
        atomicAdd(&sRd[d], sigf(f) * sCst[row*64 + d]);
    }
    __syncthreads();
    if (tid < 128) atomicAdd(&g_acc[tid], sRd[tid]);
}

// ---------- finisher ----------
__global__ void fin_kernel(const float* __restrict__ W_iouh, const float* __restrict__ b_iouh,
                           const float* __restrict__ W_oout, const float* __restrict__ b_oout,
                           float* __restrict__ out){
    __shared__ float sfc[64], shs[64], sho[64];
    int d = threadIdx.x;   // 0..63
    sfc[d] = g_acc[d];
    shs[d] = g_acc[64 + d];
    __syncthreads();
    float vi = b_iouh[d], vo = b_iouh[64 + d], vu = b_iouh[128 + d];
    #pragma unroll 8
    for (int e = 0; e < DD; e++){
        float h = shs[e];
        vi += h * W_iouh[(      d)*64 + e];
        vo += h * W_iouh[( 64 + d)*64 + e];
        vu += h * W_iouh[(128 + d)*64 + e];
    }
    float cobj = sigf(vi)*tanhp(vu) + sfc[d];
    sho[d] = sigf(vo)*tanhp(cobj);
    __syncthreads();
    float acc = b_oout[d];
    #pragma unroll 8
    for (int e = 0; e < DD; e++) acc += sho[e] * W_oout[d*64 + e];
    out[d]      = acc;
    out[64 + d] = cobj;
}

extern "C" void kernel_launch(void* const* d_in, const int* in_sizes, int n_in,
                              void* d_out, int out_size){
    const float* x      = (const float*)d_in[0];
    const float* W_num  = (const float*)d_in[1];
    const float* b_num  = (const float*)d_in[2];
    const float* W_ih   = (const float*)d_in[3];
    const float* W_hh   = (const float*)d_in[4];
    const float* b_ih   = (const float*)d_in[5];
    const float* b_hh   = (const float*)d_in[6];
    const float* W_aout = (const float*)d_in[7];
    const float* b_aout = (const float*)d_in[8];
    const float* W_fh   = (const float*)d_in[9];
    const float* b_fh   = (const float*)d_in[10];
    const float* W_iouh = (const float*)d_in[11];
    const float* b_iouh = (const float*)d_in[12];
    const float* W_oout = (const float*)d_in[13];
    const float* b_oout = (const float*)d_in[14];
    float* out = (float*)d_out;

    cudaFuncSetAttribute(lstm_kernel, cudaFuncAttributeMaxDynamicSharedMemorySize, SM_TOT);

    prep_kernel<<<1, 256>>>(W_ih, W_num, b_num, b_ih, b_hh, W_hh);
    lstm_kernel<<<NBLK, NTHR, SM_TOT>>>(x, W_aout, b_aout, W_fh, b_fh);
    fin_kernel<<<1, 64>>>(W_iouh, b_iouh, W_oout, b_oout, out);
}